// round 2
// baseline (speedup 1.0000x reference)
#include <cuda_runtime.h>
#include <math.h>

// Problem constants
#define NB 64
#define CB 64
#define DB 64
#define TB 300
#define VB 25
#define EPSB 1e-5f
#define NTOT (NB*TB)          // 19200 rows
#define FEAT (VB*DB)          // 1600 features
#define LTOT (TB+VB)          // 325
#define Y_SIZE (NB*DB*TB*VB)  // 30720000

// ---------------- scratch (device globals; no runtime allocation) ----------------
__device__ float g_xv[NB*CB*TB];        // 4.9 MB  : sum_v Wv shifted + bv
__device__ float g_xt[NB*CB*VB];        // 0.4 MB  : sum_t Wt shifted + bt
__device__ float g_part1[NB*CB*4];      // per-(n,c) partial (sv,svv,st,stt)
__device__ float g_stats1[4];           // mv, rstdv, mt, rstdt
__device__ float g_xs[NB*DB*LTOT];      // 5.3 MB  : Ws stage pre-BN
__device__ float g_part2[NB*DB*2];      // per-n per-o partials
__device__ float g_stats2[DB*2];        // mean/rstd per channel o
__device__ float g_xbar[DB*LTOT];       // mean over n of hardswished xs
__device__ float g_scale[VB*CB];        // tanh(sigmoid(view))+1, [w][c]
__device__ float g_y0[(size_t)NTOT*FEAT];  // 123 MB : pre-shift GEMM result
__device__ float g_part3[600*64];       // y0 BN partials
__device__ float g_stats3[FEAT*2];      // y0 feature mean/rstd

__device__ __forceinline__ float hswish(float x) {
    float c = fminf(fmaxf(x + 3.0f, 0.0f), 6.0f);
    return x * c * (1.0f / 6.0f);
}

// ---------------- K1: per-(n,c) slice — xv (V-reduce) + xt (T-reduce) + partials ----
__global__ void k1(const float* __restrict__ x0, const float* __restrict__ Wv,
                   const float* __restrict__ bv, const float* __restrict__ Wt,
                   const float* __restrict__ bt)
{
    __shared__ float xs_[TB*VB];   // 7500 floats
    __shared__ float wt_[TB];
    __shared__ float wvc[VB];
    __shared__ float red[64];
    __shared__ float xta[VB];

    int nc = blockIdx.x;
    int c  = nc & 63;
    int tid = threadIdx.x;

    const float* src = x0 + (size_t)nc * (TB*VB);
    for (int i = tid; i < TB*VB; i += blockDim.x) xs_[i] = src[i];
    for (int i = tid; i < TB;    i += blockDim.x) wt_[i] = Wt[i];
    if (tid < VB) {
        // wvc[v'] = Wv[(v' - c) mod 25]  (shift folded into the weight)
        int v = (tid - c) % VB; if (v < 0) v += VB;
        wvc[tid] = Wv[v];
    }
    float bvv = bv[0], btv = bt[0];
    __syncthreads();

    // xv: one dot over 25 shifted-V values per t
    float s = 0.f, ss = 0.f;
    for (int t = tid; t < TB; t += blockDim.x) {
        float a = bvv;
        #pragma unroll
        for (int v = 0; v < VB; v++) a += wvc[v] * xs_[t*VB + v];
        g_xv[nc*TB + t] = a;
        s += a; ss += a*a;
    }
    #pragma unroll
    for (int o = 16; o; o >>= 1) {
        s  += __shfl_down_sync(0xffffffffu, s,  o);
        ss += __shfl_down_sync(0xffffffffu, ss, o);
    }
    if ((tid & 31) == 0) { red[tid>>5] = s; red[32 + (tid>>5)] = ss; }
    __syncthreads();
    if (tid == 0) {
        float S = 0.f, SS = 0.f;
        for (int w = 0; w < (int)(blockDim.x >> 5); w++) { S += red[w]; SS += red[32+w]; }
        g_part1[nc*4 + 0] = S; g_part1[nc*4 + 1] = SS;
    }

    // xt: reduce over t at the shifted column v' = (v + c) % 25
    if (tid < VB) {
        int vp = tid;
        float a = btv;
        for (int t = 0; t < TB; t++) a += wt_[t] * xs_[t*VB + vp];
        int v = (vp - c) % VB; if (v < 0) v += VB;   // dest v with (v+c)%25 == vp
        g_xt[nc*VB + v] = a;
        xta[tid] = a;
    }
    __syncthreads();
    if (tid == 0) {
        float S = 0.f, SS = 0.f;
        for (int v = 0; v < VB; v++) { S += xta[v]; SS += xta[v]*xta[v]; }
        g_part1[nc*4 + 2] = S; g_part1[nc*4 + 3] = SS;
    }
}

// ---------------- K2: reduce global scalar BN stats for xv / xt ----------------
__global__ void k2()
{
    __shared__ float rw[4][8];
    int tid = threadIdx.x;
    float a0=0.f, a1=0.f, a2=0.f, a3=0.f;
    for (int i = tid; i < NB*CB; i += blockDim.x) {
        a0 += g_part1[i*4+0]; a1 += g_part1[i*4+1];
        a2 += g_part1[i*4+2]; a3 += g_part1[i*4+3];
    }
    #pragma unroll
    for (int o = 16; o; o >>= 1) {
        a0 += __shfl_down_sync(0xffffffffu, a0, o);
        a1 += __shfl_down_sync(0xffffffffu, a1, o);
        a2 += __shfl_down_sync(0xffffffffu, a2, o);
        a3 += __shfl_down_sync(0xffffffffu, a3, o);
    }
    if ((tid & 31) == 0) { int w = tid>>5; rw[0][w]=a0; rw[1][w]=a1; rw[2][w]=a2; rw[3][w]=a3; }
    __syncthreads();
    if (tid == 0) {
        float A0=0,A1=0,A2=0,A3=0;
        for (int w = 0; w < 8; w++) { A0+=rw[0][w]; A1+=rw[1][w]; A2+=rw[2][w]; A3+=rw[3][w]; }
        float cntv = (float)(NB*CB*TB);   // 1228800
        float cntt = (float)(NB*CB*VB);   // 102400
        float mv = A0/cntv, vv = A1/cntv - mv*mv;
        float mt = A2/cntt, vt = A3/cntt - mt*mt;
        g_stats1[0] = mv; g_stats1[1] = rsqrtf(vv + EPSB);
        g_stats1[2] = mt; g_stats1[3] = rsqrtf(vt + EPSB);
    }
}

// ---------------- K3: Ws stage — per-n GEMM over the concat layout + per-o partials ----
__global__ void k3(const float* __restrict__ gv, const float* __restrict__ bev,
                   const float* __restrict__ gt, const float* __restrict__ bet,
                   const float* __restrict__ Ws, const float* __restrict__ bs)
{
    extern __shared__ float sm3[];
    float* sf = sm3;            // 20800 : hardswish(bn(concat[xt,xv])) flat
    float* ws = sm3 + 20800;    // 4096

    int n = blockIdx.x, tid = threadIdx.x;
    float mv = g_stats1[0], rv = g_stats1[1], mt = g_stats1[2], rt = g_stats1[3];
    float gvv = gv[0], bevv = bev[0], gtv = gt[0], betv = bet[0];

    for (int f = tid; f < CB*LTOT; f += blockDim.x) {
        float val;
        if (f < 1600) {                 // xt block: l = c*25 + v
            int cc = f / 25, v = f % 25;
            val = g_xt[(n*64 + cc)*25 + v];
            val = gtv * (val - mt) * rt + betv;
        } else {                        // xv block: l = c*300 + t
            int f2 = f - 1600;
            int cc = f2 / 300, t = f2 % 300;
            val = g_xv[(n*64 + cc)*300 + t];
            val = gvv * (val - mv) * rv + bevv;
        }
        sf[f] = hswish(val);
    }
    for (int i = tid; i < 4096; i += blockDim.x) ws[i] = Ws[i];
    __syncthreads();

    int o  = tid >> 3;     // 512 threads: 64 channels x 8 k-slots
    int k0 = tid & 7;
    float bso = bs[o];
    float s = 0.f, ssum = 0.f;
    for (int k = k0; k < LTOT; k += 8) {
        float acc = bso;
        #pragma unroll 8
        for (int cc = 0; cc < 64; cc++) acc += ws[o*64 + cc] * sf[cc*LTOT + k];
        g_xs[(n*64 + o)*LTOT + k] = acc;
        s += acc; ssum += acc*acc;
    }
    s    += __shfl_down_sync(0xffffffffu, s, 4);
    s    += __shfl_down_sync(0xffffffffu, s, 2);
    s    += __shfl_down_sync(0xffffffffu, s, 1);
    ssum += __shfl_down_sync(0xffffffffu, ssum, 4);
    ssum += __shfl_down_sync(0xffffffffu, ssum, 2);
    ssum += __shfl_down_sync(0xffffffffu, ssum, 1);
    if ((tid & 7) == 0) {
        g_part2[(n*64 + o)*2 + 0] = s;
        g_part2[(n*64 + o)*2 + 1] = ssum;
    }
}

// ---------------- K4: per-channel stats for xs ----------------
__global__ void k4()
{
    int o = threadIdx.x;
    if (o < 64) {
        float s = 0.f, ss = 0.f;
        for (int n = 0; n < 64; n++) {
            s  += g_part2[(n*64 + o)*2 + 0];
            ss += g_part2[(n*64 + o)*2 + 1];
        }
        float cnt = 64.f * (float)LTOT;
        float m = s/cnt, v = ss/cnt - m*m;
        g_stats2[o*2 + 0] = m;
        g_stats2[o*2 + 1] = rsqrtf(v + EPSB);
    }
}

// ---------------- K5: xbar = mean_n hardswish(bn(xs)) ----------------
__global__ void k5(const float* __restrict__ gs, const float* __restrict__ bes)
{
    int idx = blockIdx.x * blockDim.x + threadIdx.x;
    if (idx >= DB*LTOT) return;
    int d = idx / LTOT, k = idx % LTOT;
    float m = g_stats2[d*2], r = g_stats2[d*2+1], g = gs[d], b = bes[d];
    float acc = 0.f;
    for (int n = 0; n < 64; n++) {
        float v = g_xs[(n*64 + d)*LTOT + k];
        acc += hswish(g * (v - m) * r + b);
    }
    g_xbar[idx] = acc * (1.0f/64.0f);
}

// ---------------- K6: x_time output (sigmoid) + view gate scale ----------------
__global__ void k6(const float* __restrict__ Wt2, const float* __restrict__ bt2,
                   const float* __restrict__ Wv2, const float* __restrict__ bv2,
                   float* __restrict__ out_xtime)
{
    int idx = blockIdx.x * blockDim.x + threadIdx.x;
    if (idx < DB*TB) {
        int o = idx / TB, l = idx % TB;
        float acc = bt2[o];
        #pragma unroll 8
        for (int d = 0; d < 64; d++) acc += Wt2[o*64 + d] * g_xbar[d*LTOT + l];
        out_xtime[idx] = 1.0f / (1.0f + expf(-acc));
    } else if (idx < DB*TB + CB*VB) {
        int j = idx - DB*TB;
        int c2 = j / 25, w = j % 25;
        float acc = bv2[c2];
        #pragma unroll 8
        for (int d = 0; d < 64; d++) acc += Wv2[c2*64 + d] * g_xbar[d*LTOT + TB + w];
        float sg = 1.0f / (1.0f + expf(-acc));
        g_scale[w*64 + c2] = tanhf(sg) + 1.0f;
    }
}

// ---------------- K7: the GEMM  y0[nt,w,dd] = sum_c x0[n,c,t,(w+c)%25]*scale[w,c]*Lw[c,dd] + Lb ----
// block: (n, 4 t-rows). 512 threads (400 compute: 25 w x 16 dd-quads), 4t x 4dd register tile.
__global__ void k7(const float* __restrict__ x0, const float* __restrict__ Lw,
                   const float* __restrict__ Lb)
{
    extern __shared__ float sm7[];
    float* xsl = sm7;            // 64 c x 100 (4t*25v) = 6400
    float* xm  = sm7 + 6400;     // 4 t x 1600 (w*64+c) = 6400
    float* lws = sm7 + 12800;    // 4096
    float* ssc = sm7 + 16896;    // 1600
    float* lbs = sm7 + 18496;    // 64

    int b = blockIdx.x;
    int n = b / 75;
    int t0 = (b % 75) * 4;
    int tid = threadIdx.x;

    const float* xbase = x0 + ((size_t)(n*64) * 300 + t0) * 25;
    for (int i = tid; i < 6400; i += blockDim.x) {
        int c = i / 100, r = i % 100;
        xsl[i] = xbase[(size_t)c * 7500 + r];
    }
    for (int i = tid; i < 4096; i += blockDim.x) lws[i] = Lw[i];
    for (int i = tid; i < 1600; i += blockDim.x) ssc[i] = g_scale[i];
    if (tid < 64) lbs[tid] = Lb[tid];
    __syncthreads();

    // build xm[t][w*64+c] = x0[n,c,t,(w+c)%25] * scale[w,c]
    for (int i = tid; i < 6400; i += blockDim.x) {
        int t = i / 1600, rem = i % 1600;
        int w = rem >> 6, c = rem & 63;
        int v = (w + c) % 25;
        xm[i] = xsl[c*100 + t*25 + v] * ssc[rem];
    }
    __syncthreads();

    if (tid < 400) {
        int dd0 = (tid & 15) << 2;   // 0..60
        int w   = tid >> 4;          // 0..24
        float acc[4][4];
        #pragma unroll
        for (int ti = 0; ti < 4; ti++)
            #pragma unroll
            for (int di = 0; di < 4; di++) acc[ti][di] = lbs[dd0 + di];

        const float* xw = xm + (w << 6);
        #pragma unroll 4
        for (int c = 0; c < 64; c++) {
            float a0 = xw[0*1600 + c];
            float a1 = xw[1*1600 + c];
            float a2 = xw[2*1600 + c];
            float a3 = xw[3*1600 + c];
            float4 bb = *(const float4*)&lws[(c << 6) + dd0];
            acc[0][0] += a0*bb.x; acc[0][1] += a0*bb.y; acc[0][2] += a0*bb.z; acc[0][3] += a0*bb.w;
            acc[1][0] += a1*bb.x; acc[1][1] += a1*bb.y; acc[1][2] += a1*bb.z; acc[1][3] += a1*bb.w;
            acc[2][0] += a2*bb.x; acc[2][1] += a2*bb.y; acc[2][2] += a2*bb.z; acc[2][3] += a2*bb.w;
            acc[3][0] += a3*bb.x; acc[3][1] += a3*bb.y; acc[3][2] += a3*bb.z; acc[3][3] += a3*bb.w;
        }
        #pragma unroll
        for (int ti = 0; ti < 4; ti++) {
            float4 o4 = make_float4(acc[ti][0], acc[ti][1], acc[ti][2], acc[ti][3]);
            *(float4*)&g_y0[(size_t)(n*300 + t0 + ti) * 1600 + (w << 6) + dd0] = o4;
        }
    }
}

// ---------------- K8: y0 per-feature BN partials (coalesced column scan) ----------------
__global__ void k8()
{
    __shared__ float sb[256], ssb[256];
    int b = blockIdx.x;          // 600 = 50 feature-groups x 12 row-chunks
    int bf = b / 12, bn = b % 12;
    int tid = threadIdx.x;
    int lane = tid & 31, wrp = tid >> 5;
    int f = bf*32 + lane;
    float s = 0.f, ss = 0.f;
    int r0 = bn * 1600;
    for (int r = r0 + wrp; r < r0 + 1600; r += 8) {
        float v = g_y0[(size_t)r * 1600 + f];
        s += v; ss += v*v;
    }
    sb[tid] = s; ssb[tid] = ss;
    __syncthreads();
    if (wrp == 0) {
        float S = sb[lane], SS = ssb[lane];
        #pragma unroll
        for (int k = 1; k < 8; k++) { S += sb[k*32 + lane]; SS += ssb[k*32 + lane]; }
        g_part3[b*64 + lane*2 + 0] = S;
        g_part3[b*64 + lane*2 + 1] = SS;
    }
}

__global__ void k8b()
{
    int f = blockIdx.x * blockDim.x + threadIdx.x;
    if (f >= FEAT) return;
    int bf = f >> 5, l = f & 31;
    float s = 0.f, ss = 0.f;
    for (int bn = 0; bn < 12; bn++) {
        s  += g_part3[(bf*12 + bn)*64 + l*2 + 0];
        ss += g_part3[(bf*12 + bn)*64 + l*2 + 1];
    }
    float cnt = (float)NTOT;
    float m = s/cnt, v = ss/cnt - m*m;
    g_stats3[f*2 + 0] = m;
    g_stats3[f*2 + 1] = rsqrtf(v + EPSB);
}

// ---------------- K9: shift + BN + residual + relu, smem-staged permutation ----------------
#define K9_TT 15
#define K9_PITCH 1632
__global__ void k9(const float* __restrict__ x0, const float* __restrict__ gbn,
                   const float* __restrict__ bbn, float* __restrict__ out)
{
    extern __shared__ float sm9[];
    float* ysm   = sm9;                       // 15 * 1632 = 24480
    float* gbn_s = sm9 + K9_TT*K9_PITCH;      // 1600
    float* bbn_s = gbn_s + 1600;              // 1600

    int b = blockIdx.x;
    int n = b / 20, t0 = (b % 20) * K9_TT;
    int tid = threadIdx.x;

    for (int i = tid; i < 1600; i += blockDim.x) { gbn_s[i] = gbn[i]; bbn_s[i] = bbn[i]; }

    // phase 1: coalesced y0 row reads, normalize with src stats, scatter by inverse shift
    for (int t = 0; t < K9_TT; t++) {
        const float* row = &g_y0[(size_t)(n*300 + t0 + t) * 1600];
        for (int p = tid; p < 1600; p += blockDim.x) {
            float v = row[p];
            v = (v - g_stats3[p*2]) * g_stats3[p*2 + 1];
            int w = p >> 6, dd = p & 63;
            int i = (w + dd) % 25;               // dest v-index
            ysm[t*K9_PITCH + i*65 + dd] = v;
        }
    }
    __syncthreads();

    // phase 2: fully coalesced output in (n, dd, t, i) layout + residual relu
    for (int idx = tid; idx < 64 * K9_TT * 25; idx += blockDim.x) {
        int dd = idx / (K9_TT*25), r = idx % (K9_TT*25);
        int t = r / 25, i = r % 25;
        int f = i*64 + dd;
        float v = fmaf(gbn_s[f], ysm[t*K9_PITCH + i*65 + dd], bbn_s[f]);
        size_t go = ((size_t)(n*64 + dd) * 300 + t0) * 25 + r;
        v += x0[go];
        out[go] = fmaxf(v, 0.0f);
    }
}

// ---------------- launcher ----------------
extern "C" void kernel_launch(void* const* d_in, const int* in_sizes, int n_in,
                              void* d_out, int out_size)
{
    const float* x0  = (const float*)d_in[0];
    // d_in[1] shift_in, d_in[2] shift_out: encoded analytically, unused
    const float* Wv  = (const float*)d_in[3];
    const float* bv  = (const float*)d_in[4];
    const float* gv  = (const float*)d_in[5];
    const float* bev = (const float*)d_in[6];
    const float* Wt  = (const float*)d_in[7];
    const float* bt  = (const float*)d_in[8];
    const float* gt  = (const float*)d_in[9];
    const float* bet = (const float*)d_in[10];
    const float* Ws  = (const float*)d_in[11];
    const float* bs  = (const float*)d_in[12];
    const float* gs  = (const float*)d_in[13];
    const float* bes = (const float*)d_in[14];
    const float* Wv2 = (const float*)d_in[15];
    const float* bv2 = (const float*)d_in[16];
    const float* Wt2 = (const float*)d_in[17];
    const float* bt2 = (const float*)d_in[18];
    const float* Lw  = (const float*)d_in[19];
    const float* Lb  = (const float*)d_in[20];
    const float* gbn = (const float*)d_in[21];
    const float* bbn = (const float*)d_in[22];
    float* out = (float*)d_out;

    static_assert(K9_TT * 20 == TB, "t tiling");

    const int smem3 = (20800 + 4096) * 4;                       // 99584
    const int smem7 = (6400 + 6400 + 4096 + 1600 + 64) * 4;     // 74240
    const int smem9 = (K9_TT*K9_PITCH + 1600 + 1600) * 4;       // 110720
    cudaFuncSetAttribute(k3, cudaFuncAttributeMaxDynamicSharedMemorySize, smem3);
    cudaFuncSetAttribute(k7, cudaFuncAttributeMaxDynamicSharedMemorySize, smem7);
    cudaFuncSetAttribute(k9, cudaFuncAttributeMaxDynamicSharedMemorySize, smem9);

    k1<<<NB*CB, 256>>>(x0, Wv, bv, Wt, bt);
    k2<<<1, 256>>>();
    k3<<<NB, 512, smem3>>>(gv, bev, gt, bet, Ws, bs);
    k4<<<1, 64>>>();
    k5<<<(DB*LTOT + 255)/256, 256>>>(gs, bes);
    k6<<<(DB*TB + CB*VB + 255)/256, 256>>>(Wt2, bt2, Wv2, bv2, out + Y_SIZE);
    k7<<<NB*75, 512, smem7>>>(x0, Lw, Lb);
    k8<<<600, 256>>>();
    k8b<<<7, 256>>>();
    k9<<<NB*20, 256, smem9>>>(x0, gbn, bbn, out);
}

// round 4
// speedup vs baseline: 1.0594x; 1.0594x over previous
#include <cuda_runtime.h>
#include <math.h>

// Problem constants
#define NB 64
#define CB 64
#define DB 64
#define TB 300
#define VB 25
#define EPSB 1e-5f
#define NTOT (NB*TB)          // 19200 rows
#define FEAT (VB*DB)          // 1600 features
#define LTOT (TB+VB)          // 325
#define Y_SIZE (NB*DB*TB*VB)  // 30720000

// ---------------- scratch (device globals; no runtime allocation) ----------------
__device__ float g_xv[NB*CB*TB];        // 4.9 MB  : sum_v Wv shifted + bv
__device__ float g_xt[NB*CB*VB];        // 0.4 MB  : sum_t Wt shifted + bt
__device__ float g_part1[NB*CB*4];      // per-(n,c) partial (sv,svv,st,stt)
__device__ float g_stats1[4];           // mv, rstdv, mt, rstdt
__device__ float g_xs[NB*DB*LTOT];      // 5.3 MB  : Ws stage pre-BN
__device__ float g_part2[320*DB*2];     // per-(n,kc) per-o partials
__device__ float g_stats2[DB*2];        // mean/rstd per channel o
__device__ float g_xbar[DB*LTOT];       // mean over n of hardswished xs
__device__ float g_scale[VB*CB];        // tanh(sigmoid(view))+1, [w][c]
__device__ float g_y0[(size_t)NTOT*FEAT];  // 123 MB : pre-shift GEMM result
__device__ float g_part3[600*64];       // y0 BN partials
__device__ float g_stats3[FEAT*2];      // y0 feature mean/rstd

__device__ __forceinline__ float hswish(float x) {
    float c = fminf(fmaxf(x + 3.0f, 0.0f), 6.0f);
    return x * c * (1.0f / 6.0f);
}

__device__ __forceinline__ unsigned long long pk2(float lo, float hi) {
    unsigned long long r;
    asm("mov.b64 %0, {%1, %2};" : "=l"(r) : "f"(lo), "f"(hi));
    return r;
}
__device__ __forceinline__ void upk2(float& lo, float& hi, unsigned long long v) {
    asm("mov.b64 {%0, %1}, %2;" : "=f"(lo), "=f"(hi) : "l"(v));
}
__device__ __forceinline__ void fma2(unsigned long long& d, unsigned long long a, unsigned long long b) {
    asm("fma.rn.f32x2 %0, %1, %2, %0;" : "+l"(d) : "l"(a), "l"(b));
}

// ---------------- K1: per-(n,c) slice — xv (V-reduce) + xt (T-reduce) + partials ----
__global__ void k1(const float* __restrict__ x0, const float* __restrict__ Wv,
                   const float* __restrict__ bv, const float* __restrict__ Wt,
                   const float* __restrict__ bt)
{
    __shared__ float xs_[TB*VB];   // 7500 floats
    __shared__ float wt_[TB];
    __shared__ float wvc[VB];
    __shared__ float red[64];
    __shared__ float xta[VB];

    int nc = blockIdx.x;
    int c  = nc & 63;
    int tid = threadIdx.x;

    const float* src = x0 + (size_t)nc * (TB*VB);
    for (int i = tid; i < TB*VB; i += blockDim.x) xs_[i] = src[i];
    for (int i = tid; i < TB;    i += blockDim.x) wt_[i] = Wt[i];
    if (tid < VB) {
        // wvc[v'] = Wv[(v' - c) mod 25]  (shift folded into the weight)
        int v = (tid - c) % VB; if (v < 0) v += VB;
        wvc[tid] = Wv[v];
    }
    float bvv = bv[0], btv = bt[0];
    __syncthreads();

    // xv: one dot over 25 shifted-V values per t
    float s = 0.f, ss = 0.f;
    for (int t = tid; t < TB; t += blockDim.x) {
        float a = bvv;
        #pragma unroll
        for (int v = 0; v < VB; v++) a += wvc[v] * xs_[t*VB + v];
        g_xv[nc*TB + t] = a;
        s += a; ss += a*a;
    }
    #pragma unroll
    for (int o = 16; o; o >>= 1) {
        s  += __shfl_down_sync(0xffffffffu, s,  o);
        ss += __shfl_down_sync(0xffffffffu, ss, o);
    }
    if ((tid & 31) == 0) { red[tid>>5] = s; red[32 + (tid>>5)] = ss; }

    // xt: reduce over t at the shifted column vp. Warps 0-6 (224 threads) all
    // execute the shfl (full-warp mask legal); lanes with vp>=25 carry zeros.
    if (tid < 224) {
        int vp = tid >> 3, sl = tid & 7;        // vp 0..27, sl 0..7
        float a = 0.f;
        if (vp < VB) {
            for (int t = sl; t < TB; t += 8) a += wt_[t] * xs_[t*VB + vp];
        }
        a += __shfl_down_sync(0xffffffffu, a, 4);
        a += __shfl_down_sync(0xffffffffu, a, 2);
        a += __shfl_down_sync(0xffffffffu, a, 1);
        if (sl == 0 && vp < VB) {
            a += btv;
            int v = (vp - c) % VB; if (v < 0) v += VB;   // dest v with (v+c)%25 == vp
            g_xt[nc*VB + v] = a;
            xta[vp] = a;
        }
    }
    __syncthreads();
    if (tid == 0) {
        float S = 0.f, SS = 0.f;
        for (int w = 0; w < (int)(blockDim.x >> 5); w++) { S += red[w]; SS += red[32+w]; }
        g_part1[nc*4 + 0] = S; g_part1[nc*4 + 1] = SS;
        S = 0.f; SS = 0.f;
        for (int v = 0; v < VB; v++) { S += xta[v]; SS += xta[v]*xta[v]; }
        g_part1[nc*4 + 2] = S; g_part1[nc*4 + 3] = SS;
    }
}

// ---------------- K2: reduce global scalar BN stats for xv / xt ----------------
__global__ void k2()
{
    __shared__ float rw[4][8];
    int tid = threadIdx.x;
    float a0=0.f, a1=0.f, a2=0.f, a3=0.f;
    for (int i = tid; i < NB*CB; i += blockDim.x) {
        a0 += g_part1[i*4+0]; a1 += g_part1[i*4+1];
        a2 += g_part1[i*4+2]; a3 += g_part1[i*4+3];
    }
    #pragma unroll
    for (int o = 16; o; o >>= 1) {
        a0 += __shfl_down_sync(0xffffffffu, a0, o);
        a1 += __shfl_down_sync(0xffffffffu, a1, o);
        a2 += __shfl_down_sync(0xffffffffu, a2, o);
        a3 += __shfl_down_sync(0xffffffffu, a3, o);
    }
    if ((tid & 31) == 0) { int w = tid>>5; rw[0][w]=a0; rw[1][w]=a1; rw[2][w]=a2; rw[3][w]=a3; }
    __syncthreads();
    if (tid == 0) {
        float A0=0,A1=0,A2=0,A3=0;
        for (int w = 0; w < 8; w++) { A0+=rw[0][w]; A1+=rw[1][w]; A2+=rw[2][w]; A3+=rw[3][w]; }
        float cntv = (float)(NB*CB*TB);
        float cntt = (float)(NB*CB*VB);
        float mv = A0/cntv, vv = A1/cntv - mv*mv;
        float mt = A2/cntt, vt = A3/cntt - mt*mt;
        g_stats1[0] = mv; g_stats1[1] = rsqrtf(vv + EPSB);
        g_stats1[2] = mt; g_stats1[3] = rsqrtf(vt + EPSB);
    }
}

// ---------------- K3: Ws stage — grid (n x 5 k-chunks), 4x4 register tiles ----------------
// concat layout: channel cc, pos k  ->  flat p = cc*325 + k;
//   p < 1600 : xt at (c=p/25, v=p%25) ;  p >= 1600 : xv at (c=(p-1600)/300, t=(p-1600)%300)
__global__ void k3(const float* __restrict__ gv, const float* __restrict__ bev,
                   const float* __restrict__ gt, const float* __restrict__ bet,
                   const float* __restrict__ Ws, const float* __restrict__ bs)
{
    extern __shared__ float sm3[];
    float* sfs    = sm3;            // [cc][68] padded k-slice of hardswish(bn(concat))
    float* wst    = sm3 + 64*68;    // transposed Ws: wst[cc*64+o]
    float* red_s  = wst + 4096;     // [17][64]
    float* red_ss = red_s + 17*64;  // [17][64]

    int b = blockIdx.x;
    int n = b / 5, kc = b % 5;
    int tid = threadIdx.x;

    float mv = g_stats1[0], rv = g_stats1[1], mt = g_stats1[2], rt = g_stats1[3];
    float gvv = gv[0], bevv = bev[0], gtv = gt[0], betv = bet[0];

    // load/transform slice: 64 cc x 65 k (+3 pad zeros)
    for (int i = tid; i < 64*68; i += blockDim.x) {
        int cc = i / 68, ll = i % 68;
        float val = 0.f;
        if (ll < 65) {
            int p = cc*LTOT + kc*65 + ll;
            if (p < 1600) {
                int cs = p / 25, v = p % 25;
                float x = g_xt[(n*64 + cs)*25 + v];
                val = hswish(gtv * (x - mt) * rt + betv);
            } else {
                int q = p - 1600;
                int cs = q / 300, t = q % 300;
                float x = g_xv[(n*64 + cs)*300 + t];
                val = hswish(gvv * (x - mv) * rv + bevv);
            }
        }
        sfs[i] = val;
    }
    for (int i = tid; i < 4096; i += blockDim.x) {
        int o = i & 63, cc = i >> 6;
        wst[i] = Ws[o*64 + cc];
    }
    __syncthreads();

    // 272 threads: og(16) x kg(17); each 4o x 4k
    if (tid < 272) {
        int og = tid & 15, kg = tid >> 4;
        int o0 = og * 4, kl0 = kg * 4;
        float acc[4][4];
        #pragma unroll
        for (int j = 0; j < 4; j++) {
            float bb = bs[o0 + j];
            #pragma unroll
            for (int i = 0; i < 4; i++) acc[j][i] = bb;
        }
        for (int cc = 0; cc < 64; cc++) {
            float4 a = *(const float4*)&wst[cc*64 + o0];
            float4 bq = *(const float4*)&sfs[cc*68 + kl0];
            acc[0][0] += a.x*bq.x; acc[0][1] += a.x*bq.y; acc[0][2] += a.x*bq.z; acc[0][3] += a.x*bq.w;
            acc[1][0] += a.y*bq.x; acc[1][1] += a.y*bq.y; acc[1][2] += a.y*bq.z; acc[1][3] += a.y*bq.w;
            acc[2][0] += a.z*bq.x; acc[2][1] += a.z*bq.y; acc[2][2] += a.z*bq.z; acc[2][3] += a.z*bq.w;
            acc[3][0] += a.w*bq.x; acc[3][1] += a.w*bq.y; acc[3][2] += a.w*bq.z; acc[3][3] += a.w*bq.w;
        }
        #pragma unroll
        for (int j = 0; j < 4; j++) {
            float s = 0.f, ssum = 0.f;
            #pragma unroll
            for (int i = 0; i < 4; i++) {
                int kl = kl0 + i;
                if (kl < 65) {
                    float v = acc[j][i];
                    g_xs[(n*64 + o0 + j)*LTOT + kc*65 + kl] = v;
                    s += v; ssum += v*v;
                }
            }
            red_s [kg*64 + o0 + j] = s;
            red_ss[kg*64 + o0 + j] = ssum;
        }
    }
    __syncthreads();
    if (tid < 64) {
        float S = 0.f, SS = 0.f;
        for (int kg = 0; kg < 17; kg++) { S += red_s[kg*64 + tid]; SS += red_ss[kg*64 + tid]; }
        g_part2[(b*64 + tid)*2 + 0] = S;
        g_part2[(b*64 + tid)*2 + 1] = SS;
    }
}

// ---------------- K4: per-channel stats for xs ----------------
__global__ void k4()
{
    int o = threadIdx.x;
    if (o < 64) {
        float s = 0.f, ss = 0.f;
        for (int ch = 0; ch < 320; ch++) {
            s  += g_part2[(ch*64 + o)*2 + 0];
            ss += g_part2[(ch*64 + o)*2 + 1];
        }
        float cnt = 64.f * (float)LTOT;
        float m = s/cnt, v = ss/cnt - m*m;
        g_stats2[o*2 + 0] = m;
        g_stats2[o*2 + 1] = rsqrtf(v + EPSB);
    }
}

// ---------------- K5: xbar = mean_n hardswish(bn(xs)) ----------------
__global__ void k5(const float* __restrict__ gs, const float* __restrict__ bes)
{
    int idx = blockIdx.x * blockDim.x + threadIdx.x;
    if (idx >= DB*LTOT) return;
    int d = idx / LTOT, k = idx % LTOT;
    float m = g_stats2[d*2], r = g_stats2[d*2+1], g = gs[d], b = bes[d];
    float acc = 0.f;
    for (int n = 0; n < 64; n++) {
        float v = g_xs[(n*64 + d)*LTOT + k];
        acc += hswish(g * (v - m) * r + b);
    }
    g_xbar[idx] = acc * (1.0f/64.0f);
}

// ---------------- K6: x_time output (sigmoid) + view gate scale ----------------
__global__ void k6(const float* __restrict__ Wt2, const float* __restrict__ bt2,
                   const float* __restrict__ Wv2, const float* __restrict__ bv2,
                   float* __restrict__ out_xtime)
{
    int idx = blockIdx.x * blockDim.x + threadIdx.x;
    if (idx < DB*TB) {
        int o = idx / TB, l = idx % TB;
        float acc = bt2[o];
        #pragma unroll 8
        for (int d = 0; d < 64; d++) acc += Wt2[o*64 + d] * g_xbar[d*LTOT + l];
        out_xtime[idx] = 1.0f / (1.0f + expf(-acc));
    } else if (idx < DB*TB + CB*VB) {
        int j = idx - DB*TB;
        int c2 = j / 25, w = j % 25;
        float acc = bv2[c2];
        #pragma unroll 8
        for (int d = 0; d < 64; d++) acc += Wv2[c2*64 + d] * g_xbar[d*LTOT + TB + w];
        float sg = 1.0f / (1.0f + expf(-acc));
        g_scale[w*64 + c2] = tanhf(sg) + 1.0f;
    }
}

// ---------------- K7: GEMM  y0[nt,w,dd] = sum_c x0[n,c,t,(w+c)%25]*scale[w,c]*Lw[c,dd]+Lb ----
// block = (n, 4 t-rows), 256 threads (200 compute: 25 w x 8 ddg), 4t x 8dd per thread, FFMA2.
#define XM_WP 66      // padded w-stride (banks differ by 2 per w)
#define XM_TP 1664    // padded t-row pitch (multiple of 4)
__global__ void k7(const float* __restrict__ x0, const float* __restrict__ Lw,
                   const float* __restrict__ Lb)
{
    extern __shared__ float sm7[];
    float* xsl = sm7;              // 64 c x 100 (4t*25v) = 6400
    float* xm  = sm7 + 6400;       // 4 t x 1664           = 6656
    float* lws = xm + 4*XM_TP;     // 4096
    float* ssc = lws + 4096;       // 1600
    float* lbs = ssc + 1600;       // 64

    int b = blockIdx.x;
    int n = b / 75;
    int t0 = (b % 75) * 4;
    int tid = threadIdx.x;

    const float* xbase = x0 + ((size_t)(n*64) * 300 + t0) * 25;
    for (int i = tid; i < 6400; i += blockDim.x) {
        int c = i / 100, r = i % 100;
        xsl[i] = xbase[(size_t)c * 7500 + r];
    }
    for (int i = tid; i < 4096; i += blockDim.x) lws[i] = Lw[i];
    for (int i = tid; i < 1600; i += blockDim.x) ssc[i] = g_scale[i];
    if (tid < 64) lbs[tid] = Lb[tid];
    __syncthreads();

    // build xm[t][w*66 + c] = x0[n,c,t,(w+c)%25] * scale[w,c]
    for (int i = tid; i < 6400; i += blockDim.x) {
        int t = i / 1600, rem = i % 1600;
        int w = rem >> 6, c = rem & 63;
        int v = (w + c) % 25;
        xm[t*XM_TP + w*XM_WP + c] = xsl[c*100 + t*25 + v] * ssc[rem];
    }
    __syncthreads();

    if (tid < 200) {
        int ddg = tid & 7;           // 8 dd-groups of 8
        int w   = tid >> 3;          // 0..24
        int dd0 = ddg << 3;
        int w66 = w * XM_WP;

        unsigned long long acc[4][4];
        #pragma unroll
        for (int p = 0; p < 4; p++) {
            unsigned long long init = pk2(lbs[dd0 + 2*p], lbs[dd0 + 2*p + 1]);
            #pragma unroll
            for (int t = 0; t < 4; t++) acc[t][p] = init;
        }

        #pragma unroll 4
        for (int c = 0; c < 64; c++) {
            float a0 = xm[0*XM_TP + w66 + c];
            float a1 = xm[1*XM_TP + w66 + c];
            float a2 = xm[2*XM_TP + w66 + c];
            float a3 = xm[3*XM_TP + w66 + c];
            unsigned long long p0 = pk2(a0, a0);
            unsigned long long p1 = pk2(a1, a1);
            unsigned long long p2 = pk2(a2, a2);
            unsigned long long p3 = pk2(a3, a3);
            ulonglong2 b01 = *(const ulonglong2*)&lws[(c << 6) + dd0];
            ulonglong2 b23 = *(const ulonglong2*)&lws[(c << 6) + dd0 + 4];
            fma2(acc[0][0], p0, b01.x); fma2(acc[0][1], p0, b01.y);
            fma2(acc[0][2], p0, b23.x); fma2(acc[0][3], p0, b23.y);
            fma2(acc[1][0], p1, b01.x); fma2(acc[1][1], p1, b01.y);
            fma2(acc[1][2], p1, b23.x); fma2(acc[1][3], p1, b23.y);
            fma2(acc[2][0], p2, b01.x); fma2(acc[2][1], p2, b01.y);
            fma2(acc[2][2], p2, b23.x); fma2(acc[2][3], p2, b23.y);
            fma2(acc[3][0], p3, b01.x); fma2(acc[3][1], p3, b01.y);
            fma2(acc[3][2], p3, b23.x); fma2(acc[3][3], p3, b23.y);
        }

        #pragma unroll
        for (int t = 0; t < 4; t++) {
            float4 o0, o1;
            upk2(o0.x, o0.y, acc[t][0]); upk2(o0.z, o0.w, acc[t][1]);
            upk2(o1.x, o1.y, acc[t][2]); upk2(o1.z, o1.w, acc[t][3]);
            float* dst = &g_y0[(size_t)(n*300 + t0 + t) * 1600 + (w << 6) + dd0];
            *(float4*)dst = o0;
            *(float4*)(dst + 4) = o1;
        }
    }
}

// ---------------- K8: y0 per-feature BN partials (coalesced column scan) ----------------
__global__ void k8()
{
    __shared__ float sb[256], ssb[256];
    int b = blockIdx.x;          // 600 = 50 feature-groups x 12 row-chunks
    int bf = b / 12, bn = b % 12;
    int tid = threadIdx.x;
    int lane = tid & 31, wrp = tid >> 5;
    int f = bf*32 + lane;
    float s = 0.f, ss = 0.f;
    int r0 = bn * 1600;
    for (int r = r0 + wrp; r < r0 + 1600; r += 8) {
        float v = g_y0[(size_t)r * 1600 + f];
        s += v; ss += v*v;
    }
    sb[tid] = s; ssb[tid] = ss;
    __syncthreads();
    if (wrp == 0) {
        float S = sb[lane], SS = ssb[lane];
        #pragma unroll
        for (int k = 1; k < 8; k++) { S += sb[k*32 + lane]; SS += ssb[k*32 + lane]; }
        g_part3[b*64 + lane*2 + 0] = S;
        g_part3[b*64 + lane*2 + 1] = SS;
    }
}

__global__ void k8b()
{
    int f = blockIdx.x * blockDim.x + threadIdx.x;
    if (f >= FEAT) return;
    int bf = f >> 5, l = f & 31;
    float s = 0.f, ss = 0.f;
    for (int bn = 0; bn < 12; bn++) {
        s  += g_part3[(bf*12 + bn)*64 + l*2 + 0];
        ss += g_part3[(bf*12 + bn)*64 + l*2 + 1];
    }
    float cnt = (float)NTOT;
    float m = s/cnt, v = ss/cnt - m*m;
    g_stats3[f*2 + 0] = m;
    g_stats3[f*2 + 1] = rsqrtf(v + EPSB);
}

// ---------------- K9: shift + BN + residual + relu, smem-staged permutation ----------------
#define K9_TT 15
#define K9_PITCH 1632
__global__ void k9(const float* __restrict__ x0, const float* __restrict__ gbn,
                   const float* __restrict__ bbn, float* __restrict__ out)
{
    extern __shared__ float sm9[];
    float* ysm   = sm9;                       // 15 * 1632 = 24480
    float* gbn_s = sm9 + K9_TT*K9_PITCH;      // 1600
    float* bbn_s = gbn_s + 1600;              // 1600

    int b = blockIdx.x;
    int n = b / 20, t0 = (b % 20) * K9_TT;
    int tid = threadIdx.x;

    for (int i = tid; i < 1600; i += blockDim.x) { gbn_s[i] = gbn[i]; bbn_s[i] = bbn[i]; }

    // phase 1: coalesced y0 row reads, normalize with src stats, scatter by inverse shift
    for (int t = 0; t < K9_TT; t++) {
        const float* row = &g_y0[(size_t)(n*300 + t0 + t) * 1600];
        for (int p = tid; p < 1600; p += blockDim.x) {
            float v = row[p];
            v = (v - g_stats3[p*2]) * g_stats3[p*2 + 1];
            int w = p >> 6, dd = p & 63;
            int i = (w + dd) % 25;               // dest v-index
            ysm[t*K9_PITCH + i*65 + dd] = v;
        }
    }
    __syncthreads();

    // phase 2: fully coalesced output in (n, dd, t, i) layout + residual relu
    for (int idx = tid; idx < 64 * K9_TT * 25; idx += blockDim.x) {
        int dd = idx / (K9_TT*25), r = idx % (K9_TT*25);
        int t = r / 25, i = r % 25;
        int f = i*64 + dd;
        float v = fmaf(gbn_s[f], ysm[t*K9_PITCH + i*65 + dd], bbn_s[f]);
        size_t go = ((size_t)(n*64 + dd) * 300 + t0) * 25 + r;
        v += x0[go];
        out[go] = fmaxf(v, 0.0f);
    }
}

// ---------------- launcher ----------------
extern "C" void kernel_launch(void* const* d_in, const int* in_sizes, int n_in,
                              void* d_out, int out_size)
{
    const float* x0  = (const float*)d_in[0];
    // d_in[1] shift_in, d_in[2] shift_out: encoded analytically, unused
    const float* Wv  = (const float*)d_in[3];
    const float* bv  = (const float*)d_in[4];
    const float* gv  = (const float*)d_in[5];
    const float* bev = (const float*)d_in[6];
    const float* Wt  = (const float*)d_in[7];
    const float* bt  = (const float*)d_in[8];
    const float* gt  = (const float*)d_in[9];
    const float* bet = (const float*)d_in[10];
    const float* Ws  = (const float*)d_in[11];
    const float* bs  = (const float*)d_in[12];
    const float* gs  = (const float*)d_in[13];
    const float* bes = (const float*)d_in[14];
    const float* Wv2 = (const float*)d_in[15];
    const float* bv2 = (const float*)d_in[16];
    const float* Wt2 = (const float*)d_in[17];
    const float* bt2 = (const float*)d_in[18];
    const float* Lw  = (const float*)d_in[19];
    const float* Lb  = (const float*)d_in[20];
    const float* gbn = (const float*)d_in[21];
    const float* bbn = (const float*)d_in[22];
    float* out = (float*)d_out;

    static_assert(K9_TT * 20 == TB, "t tiling");

    const int smem3 = (64*68 + 4096 + 17*64*2) * 4;                    // 51200
    const int smem7 = (6400 + 4*XM_TP + 4096 + 1600 + 64) * 4;         // 75264
    const int smem9 = (K9_TT*K9_PITCH + 1600 + 1600) * 4;              // 110720
    cudaFuncSetAttribute(k3, cudaFuncAttributeMaxDynamicSharedMemorySize, smem3);
    cudaFuncSetAttribute(k7, cudaFuncAttributeMaxDynamicSharedMemorySize, smem7);
    cudaFuncSetAttribute(k9, cudaFuncAttributeMaxDynamicSharedMemorySize, smem9);

    k1<<<NB*CB, 256>>>(x0, Wv, bv, Wt, bt);
    k2<<<1, 256>>>();
    k3<<<NB*5, 288, smem3>>>(gv, bev, gt, bet, Ws, bs);
    k4<<<1, 64>>>();
    k5<<<(DB*LTOT + 255)/256, 256>>>(gs, bes);
    k6<<<(DB*TB + CB*VB + 255)/256, 256>>>(Wt2, bt2, Wv2, bv2, out + Y_SIZE);
    k7<<<NB*75, 256, smem7>>>(x0, Lw, Lb);
    k8<<<600, 256>>>();
    k8b<<<7, 256>>>();
    k9<<<NB*20, 256, smem9>>>(x0, gbn, bbn, out);
}